// round 9
// baseline (speedup 1.0000x reference)
#include <cuda_runtime.h>
#include <math.h>

#define NB     256
#define NBATCH 4
#define EPS    1e-10f
#define INV_N  (1.0f / 65536.0f)

// ---------- persistent scratch (zero-init at load; re-zeroed every call) ----------
// Two slot-shifted joint streams; marginal weights ride in .z/.w:
//  JA[b][i0][j0]   += {wa1*wa2, wa1*wb2, wa1, wa2}
//  JB[b][i0+1][j0] += {wb1*wa2, wb1*wb2, wb1, wb2}
// cell(i,j) = JA[i][j].x + JA[i][j-1].y + JB[i][j].x + JB[i][j-1].y
// h1[r] = rowsum(JA.z + JB.z @ row r)
// h2[c] = colsum(JA.w @ c) + colsum(JB.w @ c-1)
__device__ float4 g_JA[NBATCH][NB][NB];        // 4 MB
__device__ float4 g_JB[NBATCH][NB][NB];        // 4 MB
__device__ float  g_h1[NBATCH * NB];
__device__ float  g_h2[NBATCH * NB];
__device__ double g_sj[NBATCH];
__device__ double g_ej[NBATCH];
__device__ float  g_mi[NBATCH];
__device__ unsigned g_tick[NBATCH];
__device__ unsigned g_done;

__device__ __forceinline__ void red4(float4* p, float a, float b, float c, float d) {
    asm volatile("red.global.add.v4.f32 [%0], {%1, %2, %3, %4};"
                 :: "l"(p), "f"(a), "f"(b), "f"(c), "f"(d) : "memory");
}

// ================= kernel 1: sparse KDE accumulation =================
// sigma=0.1 in bin units: only the two straddling bins carry weight (third
// bin <= e^-50 ~ 2e-22 relative). TWO red.v4 per pixel, nothing else:
// no shared memory, no syncs.
#define THREADS_ACC 256
#define PIX_PER_CTA 1024

__global__ __launch_bounds__(THREADS_ACC)
void mi_accum_kernel(const float* __restrict__ in1, const float* __restrict__ in2) {
    int tid = threadIdx.x;
    int base = blockIdx.x * PIX_PER_CTA;
    int b = base >> 16;

    float4 a = ((const float4*)(in1 + base))[tid];
    float4 c = ((const float4*)(in2 + base))[tid];
    const float xs1[4] = {a.x, a.y, a.z, a.w};
    const float xs2[4] = {c.x, c.y, c.z, c.w};

#pragma unroll
    for (int k = 0; k < 4; k++) {
        float x1 = xs1[k] * 255.0f;
        float x2 = xs2[k] * 255.0f;
        int i0 = min((int)floorf(x1), NB - 2);
        int j0 = min((int)floorf(x2), NB - 2);
        float f1 = x1 - (float)i0, q1 = 1.0f - f1;
        float f2 = x2 - (float)j0, q2 = 1.0f - f2;
        float wa1 = __expf(-50.0f * f1 * f1);
        float wb1 = __expf(-50.0f * q1 * q1);
        float wa2 = __expf(-50.0f * f2 * f2);
        float wb2 = __expf(-50.0f * q2 * q2);

        red4(&g_JA[b][i0][j0],     wa1 * wa2, wa1 * wb2, wa1, wa2);
        red4(&g_JB[b][i0 + 1][j0], wb1 * wa2, wb1 * wb2, wb1, wb2);
    }
}

// ================= kernel 2: fold + marginals + combine + re-zero =================
__device__ __forceinline__ float fred256(float v, float* sred) {
#pragma unroll
    for (int o = 16; o; o >>= 1) v += __shfl_xor_sync(0xffffffffu, v, o);
    int wid = threadIdx.x >> 5, lid = threadIdx.x & 31;
    if (lid == 0) sred[wid] = v;
    __syncthreads();
    float rr = 0.0f;
    if (threadIdx.x < 32) {
        rr = (threadIdx.x < 8) ? sred[threadIdx.x] : 0.0f;
#pragma unroll
        for (int o = 4; o; o >>= 1) rr += __shfl_xor_sync(0xffffffffu, rr, o);
        if (threadIdx.x == 0) sred[0] = rr;
    }
    __syncthreads();
    float out = sred[0];
    __syncthreads();
    return out;
}

// 256 CTAs x 256 thr. CTA (rb, sub) owns cell rows [4sub..4sub+3] of batch rb
// (the FULL rows: 64 threads x 4 cells = 256 cols). All reads (incl. neighbor
// .y) happen before __syncthreads; zeroing after -> no races (all intra-CTA).
__global__ __launch_bounds__(256)
void mi_reduce_final_kernel(float* __restrict__ out) {
    __shared__ float sred[8];
    __shared__ float srow[4];
    __shared__ float scolA[NB];
    __shared__ float scolB[NB];
    __shared__ int   sflag;
    int tid = threadIdx.x;
    int rb  = blockIdx.x >> 6;
    int sub = blockIdx.x & 63;

    int row = 4 * sub + (tid >> 6);
    int c0  = (tid & 63) * 4;

    if (tid < 4) srow[tid] = 0.0f;
    scolA[tid] = 0.0f;
    scolB[tid] = 0.0f;

    float4* Ap = &g_JA[rb][row][0];
    float4* Bp = &g_JB[rb][row][0];
    float4 A0 = Ap[c0], A1 = Ap[c0+1], A2 = Ap[c0+2], A3 = Ap[c0+3];
    float4 B0 = Bp[c0], B1 = Bp[c0+1], B2 = Bp[c0+2], B3 = Bp[c0+3];
    float aprev = (c0 == 0) ? 0.0f : Ap[c0 - 1].y;
    float bprev = (c0 == 0) ? 0.0f : Bp[c0 - 1].y;

    __syncthreads();                      // all loads done (incl. neighbor .y)
    float4 z4 = make_float4(0.f, 0.f, 0.f, 0.f);
    Ap[c0] = z4; Ap[c0+1] = z4; Ap[c0+2] = z4; Ap[c0+3] = z4;
    Bp[c0] = z4; Bp[c0+1] = z4; Bp[c0+2] = z4; Bp[c0+3] = z4;

    float v0 = (A0.x + aprev) + (B0.x + bprev);
    float v1 = (A1.x + A0.y) + (B1.x + B0.y);
    float v2 = (A2.x + A1.y) + (B2.x + B1.y);
    float v3 = (A3.x + A2.y) + (B3.x + B2.y);

    float sj = (v0 + v1) + (v2 + v3);
    float ej = v0 * __log2f(v0 + EPS)
             + v1 * __log2f(v1 + EPS)
             + v2 * __log2f(v2 + EPS)
             + v3 * __log2f(v3 + EPS);

    // marginal partials
    float za = ((A0.z + A1.z) + (A2.z + A3.z)) + ((B0.z + B1.z) + (B2.z + B3.z));
    atomicAdd(&srow[row & 3], za);
    atomicAdd(&scolA[c0],     A0.w);
    atomicAdd(&scolA[c0 + 1], A1.w);
    atomicAdd(&scolA[c0 + 2], A2.w);
    atomicAdd(&scolA[c0 + 3], A3.w);
    atomicAdd(&scolB[c0],     B0.w);
    atomicAdd(&scolB[c0 + 1], B1.w);
    atomicAdd(&scolB[c0 + 2], B2.w);
    atomicAdd(&scolB[c0 + 3], B3.w);

    sj = fred256(sj, sred);               // internal syncs also fence smem atomics
    ej = fred256(ej, sred);
    if (tid == 0) {
        atomicAdd(&g_sj[rb], (double)sj);
        atomicAdd(&g_ej[rb], (double)ej);
    }

    // h1: full row lives in this CTA -> plain store, no atomic
    if (tid < 4) g_h1[rb * NB + 4 * sub + tid] = srow[tid];
    // h2: per-CTA partial across columns -> global atomic
    float h2p = scolA[tid] + ((tid > 0) ? scolB[tid - 1] : 0.0f);
    atomicAdd(&g_h2[rb * NB + tid], h2p);

    // ---- per-batch finalizer (ticket: all 64 CTAs of batch rb done) ----
    __threadfence();
    __syncthreads();
    if (tid == 0) {
        unsigned t = atomicAdd(&g_tick[rb], 1u);
        sflag = (t == 63u);
    }
    __syncthreads();
    if (sflag) {
        __threadfence();
        float h1 = g_h1[rb * NB + tid];
        float h2 = g_h2[rb * NB + tid];
        g_h1[rb * NB + tid] = 0.0f;       // re-zero for next replay
        g_h2[rb * NB + tid] = 0.0f;
        float m1 = h1 * INV_N;
        float m2 = h2 * INV_N;
        float S1 = fred256(m1, sred);
        float S2 = fred256(m2, sred);
        float p1v = m1 / (S1 + EPS);
        float p2v = m2 / (S2 + EPS);
        float e1 = fred256(p1v * __log2f(p1v + EPS), sred);
        float e2 = fred256(p2v * __log2f(p2v + EPS), sred);
        if (tid == 0) {
            double Sj = g_sj[rb];
            double Ej = g_ej[rb];
            double den = Sj + (double)EPS;
            // Hj = -sum q*log2(q+eps), q=j/(Sj+eps), factored single-pass
            double Hj = -(Ej - Sj * log2(den)) / den;
            double H1 = (double)(-e1);
            double H2 = (double)(-e2);
            g_mi[rb] = (float)(2.0 * (H1 + H2 - Hj) / (H1 + H2));
            g_sj[rb] = 0.0; g_ej[rb] = 0.0; g_tick[rb] = 0u;
            __threadfence();
            unsigned d = atomicAdd(&g_done, 1u);
            if (d == (unsigned)(NBATCH - 1)) {
                __threadfence();
                out[0] = 0.25f * (g_mi[0] + g_mi[1] + g_mi[2] + g_mi[3]);
                g_done = 0u;
            }
        }
    }
}

// ================= launch: 2 kernels =================
extern "C" void kernel_launch(void* const* d_in, const int* in_sizes, int n_in,
                              void* d_out, int out_size) {
    const float* in1 = (const float*)d_in[0];
    const float* in2 = (const float*)d_in[1];
    float* out = (float*)d_out;

    mi_accum_kernel<<<(NBATCH * 65536) / PIX_PER_CTA, THREADS_ACC>>>(in1, in2);
    mi_reduce_final_kernel<<<256, 256>>>(out);
}

// round 10
// speedup vs baseline: 1.3672x; 1.3672x over previous
#include <cuda_runtime.h>
#include <math.h>

#define NB     256
#define NPB    65536
#define NBATCH 4
#define EPS    1e-10f
#define INV_N  (1.0f / 65536.0f)

// ---------- persistent scratch (zero-init at load; re-zeroed every call) ----------
// Slot-shifted joint: J2[b][i][j][0] feeds cell (i,j), J2[b][i][j][1] feeds (i,j+1).
__device__ float  g_J2[NBATCH][NB][NB][2];     // 2 MB
__device__ float  g_h1[NBATCH * NB];
__device__ float  g_h2[NBATCH * NB];
__device__ double g_sj[NBATCH];
__device__ double g_ej[NBATCH];
__device__ float  g_H1[NBATCH], g_H2[NBATCH];
__device__ unsigned g_bar1;

__device__ __forceinline__ void red2(float* p, float a, float b) {
    asm volatile("red.global.add.v2.f32 [%0], {%1, %2};"
                 :: "l"(p), "f"(a), "f"(b) : "memory");
}

// ================= kernel 1: sparse KDE accumulation (R7 baseline) =================
// sigma=0.1 in bin units: only the two straddling bins carry weight (third
// bin <= e^-50 ~ 2e-22 relative). Joint: 2 aligned red.v2 per pixel into the
// slot-shifted layout. Marginals: shared-memory atomics.
#define THREADS_ACC 256
#define PIX_PER_CTA 1024

__global__ __launch_bounds__(THREADS_ACC)
void mi_accum_kernel(const float* __restrict__ in1, const float* __restrict__ in2) {
    __shared__ float sh1[NB];
    __shared__ float sh2[NB];
    int tid = threadIdx.x;
    int base = blockIdx.x * PIX_PER_CTA;
    int b = base >> 16;

    float4 a = ((const float4*)(in1 + base))[tid];
    float4 c = ((const float4*)(in2 + base))[tid];

    sh1[tid] = 0.0f;
    sh2[tid] = 0.0f;
    __syncthreads();

    const float xs1[4] = {a.x, a.y, a.z, a.w};
    const float xs2[4] = {c.x, c.y, c.z, c.w};

#pragma unroll
    for (int k = 0; k < 4; k++) {
        float x1 = xs1[k] * 255.0f;
        float x2 = xs2[k] * 255.0f;
        int i0 = min((int)floorf(x1), NB - 2);
        int j0 = min((int)floorf(x2), NB - 2);
        float f1 = x1 - (float)i0, q1 = 1.0f - f1;
        float f2 = x2 - (float)j0, q2 = 1.0f - f2;
        float wa1 = __expf(-50.0f * f1 * f1);
        float wb1 = __expf(-50.0f * q1 * q1);
        float wa2 = __expf(-50.0f * f2 * f2);
        float wb2 = __expf(-50.0f * q2 * q2);

        red2(&g_J2[b][i0][j0][0],     wa1 * wa2, wa1 * wb2);
        red2(&g_J2[b][i0 + 1][j0][0], wb1 * wa2, wb1 * wb2);

        atomicAdd(&sh1[i0],     wa1);
        atomicAdd(&sh1[i0 + 1], wb1);
        atomicAdd(&sh2[j0],     wa2);
        atomicAdd(&sh2[j0 + 1], wb2);
    }

    __syncthreads();
    atomicAdd(&g_h1[b * NB + tid], sh1[tid]);
    atomicAdd(&g_h2[b * NB + tid], sh2[tid]);
}

// ================= kernel 2: PDL reduce + combine + re-zero =================
// Launched with ProgrammaticStreamSerialization: CTAs roll out during accum,
// griddepcontrol.wait gates the scratch reads on accum's completion flush.

// merged float2 block reduction over 256 threads (one set of barriers)
__device__ __forceinline__ float2 fred256x2(float va, float vb, float2* sred) {
#pragma unroll
    for (int o = 16; o; o >>= 1) {
        va += __shfl_xor_sync(0xffffffffu, va, o);
        vb += __shfl_xor_sync(0xffffffffu, vb, o);
    }
    int wid = threadIdx.x >> 5, lid = threadIdx.x & 31;
    if (lid == 0) sred[wid] = make_float2(va, vb);
    __syncthreads();
    if (threadIdx.x < 32) {
        float ra = (threadIdx.x < 8) ? sred[threadIdx.x].x : 0.0f;
        float rb = (threadIdx.x < 8) ? sred[threadIdx.x].y : 0.0f;
#pragma unroll
        for (int o = 4; o; o >>= 1) {
            ra += __shfl_xor_sync(0xffffffffu, ra, o);
            rb += __shfl_xor_sync(0xffffffffu, rb, o);
        }
        if (threadIdx.x == 0) sred[0] = make_float2(ra, rb);
    }
    __syncthreads();
    float2 out = sred[0];
    __syncthreads();
    return out;
}

__global__ __launch_bounds__(256)
void mi_reduce_final_kernel(float* __restrict__ out) {
    __shared__ float2 sred[8];
    int tid = threadIdx.x;
    int rb  = blockIdx.x >> 6;
    int sub = blockIdx.x & 63;

    int row   = 4 * sub + (tid >> 6);
    int cell0 = (tid & 63) * 4;
    float* rowp = &g_J2[rb][row][0][0];      // 512 floats per row

    // ---- wait for accum completion (PDL); no-op under plain launch ----
    asm volatile("griddepcontrol.wait;" ::: "memory");

    float4 p0 = *(float4*)(rowp + cell0 * 2);        // slots c0, c0+1
    float4 p1 = *(float4*)(rowp + cell0 * 2 + 4);    // slots c0+2, c0+3
    float prev = (cell0 == 0) ? 0.0f : rowp[cell0 * 2 - 1];   // [c0-1][1]

    __syncthreads();                          // all reads before any zeroing
    *(float4*)(rowp + cell0 * 2)     = make_float4(0.f, 0.f, 0.f, 0.f);
    *(float4*)(rowp + cell0 * 2 + 4) = make_float4(0.f, 0.f, 0.f, 0.f);

    float v0 = p0.x + prev;
    float v1 = p0.z + p0.y;
    float v2 = p1.x + p0.w;
    float v3 = p1.z + p1.y;                   // p1.w feeds next thread's v0

    float sj = (v0 + v1) + (v2 + v3);
    float ej = v0 * __log2f(v0 + EPS)
             + v1 * __log2f(v1 + EPS)
             + v2 * __log2f(v2 + EPS)
             + v3 * __log2f(v3 + EPS);

    float2 se = fred256x2(sj, ej, sred);
    if (tid == 0) {
        atomicAdd(&g_sj[rb], (double)se.x);
        atomicAdd(&g_ej[rb], (double)se.y);
    }

    // marginals: exact reference math, one CTA per batch
    if (sub == 0) {
        float h1 = __ldcg(&g_h1[rb * NB + tid]);
        float h2 = __ldcg(&g_h2[rb * NB + tid]);
        g_h1[rb * NB + tid] = 0.0f;           // same-thread read-then-zero
        g_h2[rb * NB + tid] = 0.0f;
        float m1 = h1 * INV_N;
        float m2 = h2 * INV_N;
        float2 S = fred256x2(m1, m2, sred);
        float p1v = m1 / (S.x + EPS);
        float p2v = m2 / (S.y + EPS);
        float2 E = fred256x2(p1v * __log2f(p1v + EPS),
                             p2v * __log2f(p2v + EPS), sred);
        if (tid == 0) { g_H1[rb] = -E.x; g_H2[rb] = -E.y; }
    }

    // last-block combine + reset
    __threadfence();
    __syncthreads();
    if (tid == 0) {
        unsigned t = atomicAdd(&g_bar1, 1u);
        if (t == 255u) {
            __threadfence();
            double acc = 0.0;
#pragma unroll
            for (int bb = 0; bb < NBATCH; bb++) {
                double Sj = g_sj[bb];
                double Ej = g_ej[bb];
                double den = Sj + (double)EPS;
                // Hj = -sum q*log2(q+eps), q=j/(Sj+eps), factored single-pass
                double Hj = -(Ej - Sj * log2(den)) / den;
                double H1 = (double)g_H1[bb];
                double H2 = (double)g_H2[bb];
                acc += 2.0 * (H1 + H2 - Hj) / (H1 + H2);
                g_sj[bb] = 0.0; g_ej[bb] = 0.0;
                g_H1[bb] = 0.0f; g_H2[bb] = 0.0f;
            }
            out[0] = (float)(acc * 0.25);
            g_bar1 = 0u;
        }
    }
}

// ================= launch: 2 kernels, second via PDL =================
extern "C" void kernel_launch(void* const* d_in, const int* in_sizes, int n_in,
                              void* d_out, int out_size) {
    const float* in1 = (const float*)d_in[0];
    const float* in2 = (const float*)d_in[1];
    float* out = (float*)d_out;

    mi_accum_kernel<<<(NBATCH * NPB) / PIX_PER_CTA, THREADS_ACC>>>(in1, in2);

    cudaLaunchConfig_t cfg = {};
    cfg.gridDim  = dim3(256, 1, 1);
    cfg.blockDim = dim3(256, 1, 1);
    cudaLaunchAttribute attr[1];
    attr[0].id = cudaLaunchAttributeProgrammaticStreamSerialization;
    attr[0].val.programmaticStreamSerializationAllowed = 1;
    cfg.attrs = attr;
    cfg.numAttrs = 1;
    cudaError_t e = cudaLaunchKernelEx(&cfg, mi_reduce_final_kernel, out);
    if (e != cudaSuccess) {
        // PDL rejected (e.g. by capture) -> plain launch fallback
        mi_reduce_final_kernel<<<256, 256>>>(out);
    }
}